// round 3
// baseline (speedup 1.0000x reference)
#include <cuda_runtime.h>
#include <math.h>

#define TPB 256

// Partial per-row sums (B <= 65536 supported; actual B = 16384).
__device__ float g_partials[65536];
__device__ unsigned int g_count = 0;

__device__ __forceinline__ float warp_sum(float v) {
#pragma unroll
    for (int o = 16; o > 0; o >>= 1) v += __shfl_xor_sync(0xffffffffu, v, o);
    return v;
}
__device__ __forceinline__ float warp_max(float v) {
#pragma unroll
    for (int o = 16; o > 0; o >>= 1) v = fmaxf(v, __shfl_xor_sync(0xffffffffu, v, o));
    return v;
}
__device__ __forceinline__ double warp_sum_d(double v) {
#pragma unroll
    for (int o = 16; o > 0; o >>= 1) v += __shfl_xor_sync(0xffffffffu, v, o);
    return v;
}

// Block reductions over TPB=256 threads (8 warps). sred must be 8 floats.
__device__ __forceinline__ float block_sum(float v, float* sred) {
    int tid = threadIdx.x;
    v = warp_sum(v);
    __syncthreads();                 // protect sred reuse across calls
    if ((tid & 31) == 0) sred[tid >> 5] = v;
    __syncthreads();
    float r = sred[0];
#pragma unroll
    for (int i = 1; i < TPB / 32; i++) r += sred[i];
    return r;
}
__device__ __forceinline__ float block_max(float v, float* sred) {
    int tid = threadIdx.x;
    v = warp_max(v);
    __syncthreads();
    if ((tid & 31) == 0) sred[tid >> 5] = v;
    __syncthreads();
    float r = sred[0];
#pragma unroll
    for (int i = 1; i < TPB / 32; i++) r = fmaxf(r, sred[i]);
    return r;
}

__device__ __forceinline__ float loss_elem(float x, float m, float logsum,
                                           float e, float inv_s, float y) {
    const float EPSF  = 1e-7f;
    const float ONEM  = 1.0f - 1e-7f;
    float t = (x - m) - logsum;        // log p (unclipped), free
    float p = e * inv_s;               // softmax prob
    float pc = fminf(fmaxf(p, EPSF), ONEM);
    float logp = (p >= EPSF && p <= ONEM) ? t : __logf(pc);
    float l1m;
    if (pc < 0.04f) {
        l1m = -pc * (1.0f + pc * (0.5f + pc * (0.33333334f + pc * 0.25f)));
    } else {
        l1m = __logf(1.0f - pc);
    }
    return fmaf(y, logp, (1.0f - y) * l1m);
}

// Fused deterministic final reduce, executed by the LAST block to finish.
// Election order is nondeterministic, but the elected block computes the
// full sum alone in a fixed order -> output is deterministic.
__device__ __forceinline__ void fused_final(float* out, int Bv, double denom,
                                            int tid) {
    __shared__ unsigned int s_last;
    if (tid == 0) {
        __threadfence();
        unsigned int old = atomicAdd(&g_count, 1u);
        s_last = (old == (unsigned int)gridDim.x - 1u) ? 1u : 0u;
    }
    __syncthreads();
    if (!s_last) return;

    int B4 = Bv & ~3;
    double a0 = 0.0, a1 = 0.0, a2 = 0.0, a3 = 0.0;
    for (int i = 4 * tid; i < B4; i += 4 * TPB) {
        float4 v = *(const float4*)(g_partials + i);
        a0 += (double)v.x; a1 += (double)v.y;
        a2 += (double)v.z; a3 += (double)v.w;
    }
    for (int i = B4 + tid; i < Bv; i += TPB) a0 += (double)g_partials[i];
    double a = (a0 + a1) + (a2 + a3);
    a = warp_sum_d(a);
    __shared__ double sdd[TPB / 32];
    if ((tid & 31) == 0) sdd[tid >> 5] = a;
    __syncthreads();
    if (tid == 0) {
        double t = sdd[0];
#pragma unroll
        for (int i = 1; i < TPB / 32; i++) t += sdd[i];
        out[0] = (float)(t / denom);
        g_count = 0;                 // re-arm for next graph replay
    }
}

// Fast path: C == 4096, one block of 256 threads per row, 16 elems/thread in regs.
__global__ void __launch_bounds__(TPB, 3)
wvce_row4096(const float* __restrict__ y_pred, const float* __restrict__ y_true,
             const float* __restrict__ weights, const int* __restrict__ cond,
             int nbins, float* __restrict__ out) {
    const int C = 4096;
    int row = blockIdx.x;
    int tid = threadIdx.x;
    const float4* xp = (const float4*)(y_pred + (size_t)row * C);
    const float4* yp = (const float4*)(y_true + (size_t)row * C);

    __shared__ float sred[TPB / 32];

    float4 x[4];
    float lmax = -INFINITY;
#pragma unroll
    for (int k = 0; k < 4; k++) {
        x[k] = xp[tid + k * TPB];
        lmax = fmaxf(lmax, fmaxf(fmaxf(x[k].x, x[k].y), fmaxf(x[k].z, x[k].w)));
    }
    float m = block_max(lmax, sred);

    float4 e[4];
    float lsum = 0.0f;
#pragma unroll
    for (int k = 0; k < 4; k++) {
        e[k].x = __expf(x[k].x - m);
        e[k].y = __expf(x[k].y - m);
        e[k].z = __expf(x[k].z - m);
        e[k].w = __expf(x[k].w - m);
        lsum += (e[k].x + e[k].y) + (e[k].z + e[k].w);
    }
    float s = block_sum(lsum, sred);
    float logsum = __logf(s);
    float inv_s = 1.0f / s;

    // Batch all y loads up front for memory-level parallelism.
    float4 y[4];
#pragma unroll
    for (int k = 0; k < 4; k++) y[k] = yp[tid + k * TPB];

    float acc = 0.0f;
#pragma unroll
    for (int k = 0; k < 4; k++) {
        acc += loss_elem(x[k].x, m, logsum, e[k].x, inv_s, y[k].x);
        acc += loss_elem(x[k].y, m, logsum, e[k].y, inv_s, y[k].y);
        acc += loss_elem(x[k].z, m, logsum, e[k].z, inv_s, y[k].z);
        acc += loss_elem(x[k].w, m, logsum, e[k].w, inv_s, y[k].w);
    }
    float rowsum = block_sum(acc, sred);
    if (tid == 0) {
        int bi = cond[row];
        bi = max(0, min(bi, nbins - 1));     // clamp: never fault on bad data
        float w = weights[bi];
        g_partials[row] = -w * rowsum;
    }

    fused_final(out, gridDim.x, (double)gridDim.x * (double)C, tid);
}

// Generic fallback (any C): 3 passes re-reading gmem. Correctness safety net.
__global__ void __launch_bounds__(TPB)
wvce_row_generic(const float* __restrict__ y_pred, const float* __restrict__ y_true,
                 const float* __restrict__ weights, const int* __restrict__ cond,
                 int C, int nbins, float* __restrict__ out) {
    int row = blockIdx.x;
    int tid = threadIdx.x;
    const float* xp = y_pred + (size_t)row * C;
    const float* yp = y_true + (size_t)row * C;
    __shared__ float sred[TPB / 32];

    float lmax = -INFINITY;
    for (int i = tid; i < C; i += TPB) lmax = fmaxf(lmax, xp[i]);
    float m = block_max(lmax, sred);

    float lsum = 0.0f;
    for (int i = tid; i < C; i += TPB) lsum += __expf(xp[i] - m);
    float s = block_sum(lsum, sred);
    float logsum = __logf(s);
    float inv_s = 1.0f / s;

    float acc = 0.0f;
    for (int i = tid; i < C; i += TPB) {
        float x = xp[i];
        float e = __expf(x - m);
        acc += loss_elem(x, m, logsum, e, inv_s, yp[i]);
    }
    float rowsum = block_sum(acc, sred);
    if (tid == 0) {
        int bi = cond[row];
        bi = max(0, min(bi, nbins - 1));
        float w = weights[bi];
        g_partials[row] = -w * rowsum;
    }

    fused_final(out, gridDim.x, (double)gridDim.x * (double)C, tid);
}

extern "C" void kernel_launch(void* const* d_in, const int* in_sizes, int n_in,
                              void* d_out, int out_size) {
    const float* y_pred  = (const float*)d_in[0];
    const float* y_true  = (const float*)d_in[1];
    const float* weights = (const float*)d_in[2];
    const int*   cond    = (const int*)d_in[3];   // JAX x64 disabled -> int32

    int B     = in_sizes[3];
    int nbins = in_sizes[2];
    int C     = in_sizes[0] / B;

    if (C == 4096) {
        wvce_row4096<<<B, TPB>>>(y_pred, y_true, weights, cond, nbins,
                                 (float*)d_out);
    } else {
        wvce_row_generic<<<B, TPB>>>(y_pred, y_true, weights, cond, C, nbins,
                                     (float*)d_out);
    }
}

// round 4
// speedup vs baseline: 1.1770x; 1.1770x over previous
#include <cuda_runtime.h>
#include <math.h>

#define TPB 256

// Partial per-row sums (B <= 65536 supported; actual B = 16384).
__device__ float g_partials[65536];

__device__ __forceinline__ float warp_sum(float v) {
#pragma unroll
    for (int o = 16; o > 0; o >>= 1) v += __shfl_xor_sync(0xffffffffu, v, o);
    return v;
}
__device__ __forceinline__ float warp_max(float v) {
#pragma unroll
    for (int o = 16; o > 0; o >>= 1) v = fmaxf(v, __shfl_xor_sync(0xffffffffu, v, o));
    return v;
}
__device__ __forceinline__ double warp_sum_d(double v) {
#pragma unroll
    for (int o = 16; o > 0; o >>= 1) v += __shfl_xor_sync(0xffffffffu, v, o);
    return v;
}

__device__ __forceinline__ float block_sum(float v, float* sred) {
    int tid = threadIdx.x;
    v = warp_sum(v);
    __syncthreads();
    if ((tid & 31) == 0) sred[tid >> 5] = v;
    __syncthreads();
    float r = sred[0];
#pragma unroll
    for (int i = 1; i < TPB / 32; i++) r += sred[i];
    return r;
}
__device__ __forceinline__ float block_max(float v, float* sred) {
    int tid = threadIdx.x;
    v = warp_max(v);
    __syncthreads();
    if ((tid & 31) == 0) sred[tid >> 5] = v;
    __syncthreads();
    float r = sred[0];
#pragma unroll
    for (int i = 1; i < TPB / 32; i++) r = fmaxf(r, sred[i]);
    return r;
}

// BCE element given u = x - rowmax and logsum. p is recomputed (1 MUFU).
// log(clip(p)) == clamp(log p, log eps, log(1-eps)) exactly (log monotone),
// so no log is ever evaluated for the logp term.
__device__ __forceinline__ float loss_elem_u(float u, float logsum, float y) {
    const float LOG_EPS  = -16.11809565f;    // log(1e-7)
    const float LOG_ONEM = -1.00000005e-7f;  // log(1 - 1e-7)
    const float EPSF = 1e-7f;
    const float ONEM = 1.0f - 1e-7f;
    float t = u - logsum;                      // log p (unclipped)
    float logp = fminf(fmaxf(t, LOG_EPS), LOG_ONEM);
    float p = __expf(t);
    float pc = fminf(fmaxf(p, EPSF), ONEM);
    float l1m;
    if (pc < 0.04f) {                          // p_max ~ 1e-2 for this data
        l1m = -pc * (1.0f + pc * (0.5f + pc * (0.33333334f + pc * 0.25f)));
    } else {
        l1m = __logf(1.0f - pc);
    }
    return fmaf(y, logp - l1m, l1m);           // y*logp + (1-y)*l1m
}

// Fast path: C == 4096, one block of 256 threads per row, 16 elems/thread.
// Only u[16] stays live across syncs -> low register pressure, high occupancy.
__global__ void __launch_bounds__(TPB, 5)
wvce_row4096(const float* __restrict__ y_pred, const float* __restrict__ y_true,
             const float* __restrict__ weights, const int* __restrict__ cond,
             int nbins) {
    const int C = 4096;
    int row = blockIdx.x;
    int tid = threadIdx.x;
    const float4* xp = (const float4*)(y_pred + (size_t)row * C);
    const float4* yp = (const float4*)(y_true + (size_t)row * C);

    __shared__ float sred[TPB / 32];

    float4 u[4];
    float lmax = -INFINITY;
#pragma unroll
    for (int k = 0; k < 4; k++) {
        u[k] = xp[tid + k * TPB];
        lmax = fmaxf(lmax, fmaxf(fmaxf(u[k].x, u[k].y), fmaxf(u[k].z, u[k].w)));
    }
    float m = block_max(lmax, sred);

    float lsum = 0.0f;
#pragma unroll
    for (int k = 0; k < 4; k++) {
        u[k].x -= m; u[k].y -= m; u[k].z -= m; u[k].w -= m;
        float e0 = __expf(u[k].x), e1 = __expf(u[k].y);
        float e2 = __expf(u[k].z), e3 = __expf(u[k].w);
        lsum += (e0 + e1) + (e2 + e3);
    }
    float s = block_sum(lsum, sred);
    float logsum = __logf(s);

    float acc = 0.0f;
#pragma unroll
    for (int k = 0; k < 4; k++) {
        float4 y4 = yp[tid + k * TPB];
        acc += loss_elem_u(u[k].x, logsum, y4.x);
        acc += loss_elem_u(u[k].y, logsum, y4.y);
        acc += loss_elem_u(u[k].z, logsum, y4.z);
        acc += loss_elem_u(u[k].w, logsum, y4.w);
    }
    float rowsum = block_sum(acc, sred);
    if (tid == 0) {
        int bi = cond[row];
        bi = max(0, min(bi, nbins - 1));   // clamp: never fault on bad data
        g_partials[row] = -weights[bi] * rowsum;
    }
}

// Generic fallback (any C): 3 passes re-reading gmem. Correctness safety net.
__global__ void __launch_bounds__(TPB)
wvce_row_generic(const float* __restrict__ y_pred, const float* __restrict__ y_true,
                 const float* __restrict__ weights, const int* __restrict__ cond,
                 int C, int nbins) {
    int row = blockIdx.x;
    int tid = threadIdx.x;
    const float* xp = y_pred + (size_t)row * C;
    const float* yp = y_true + (size_t)row * C;
    __shared__ float sred[TPB / 32];

    float lmax = -INFINITY;
    for (int i = tid; i < C; i += TPB) lmax = fmaxf(lmax, xp[i]);
    float m = block_max(lmax, sred);

    float lsum = 0.0f;
    for (int i = tid; i < C; i += TPB) lsum += __expf(xp[i] - m);
    float s = block_sum(lsum, sred);
    float logsum = __logf(s);

    float acc = 0.0f;
    for (int i = tid; i < C; i += TPB)
        acc += loss_elem_u(xp[i] - m, logsum, yp[i]);
    float rowsum = block_sum(acc, sred);
    if (tid == 0) {
        int bi = cond[row];
        bi = max(0, min(bi, nbins - 1));
        g_partials[row] = -weights[bi] * rowsum;
    }
}

// Fast deterministic final reduce: one block, float4 loads (MLP=16),
// 4 independent double accumulators -> no serial dependent chain.
__global__ void __launch_bounds__(TPB)
wvce_final(float* __restrict__ out, int B, int C) {
    int tid = threadIdx.x;
    int B4 = B & ~3;
    double a0 = 0.0, a1 = 0.0, a2 = 0.0, a3 = 0.0;
    for (int i = 4 * tid; i < B4; i += 4 * TPB) {
        float4 v = *(const float4*)(g_partials + i);
        a0 += (double)v.x; a1 += (double)v.y;
        a2 += (double)v.z; a3 += (double)v.w;
    }
    for (int i = B4 + tid; i < B; i += TPB) a0 += (double)g_partials[i];
    double a = (a0 + a1) + (a2 + a3);
    a = warp_sum_d(a);
    __shared__ double sdd[TPB / 32];
    if ((tid & 31) == 0) sdd[tid >> 5] = a;
    __syncthreads();
    if (tid == 0) {
        double t = sdd[0];
#pragma unroll
        for (int i = 1; i < TPB / 32; i++) t += sdd[i];
        out[0] = (float)(t / ((double)B * (double)C));
    }
}

extern "C" void kernel_launch(void* const* d_in, const int* in_sizes, int n_in,
                              void* d_out, int out_size) {
    const float* y_pred  = (const float*)d_in[0];
    const float* y_true  = (const float*)d_in[1];
    const float* weights = (const float*)d_in[2];
    const int*   cond    = (const int*)d_in[3];   // JAX x64 disabled -> int32

    int B     = in_sizes[3];
    int nbins = in_sizes[2];
    int C     = in_sizes[0] / B;

    if (C == 4096) {
        wvce_row4096<<<B, TPB>>>(y_pred, y_true, weights, cond, nbins);
    } else {
        wvce_row_generic<<<B, TPB>>>(y_pred, y_true, weights, cond, C, nbins);
    }
    wvce_final<<<1, TPB>>>((float*)d_out, B, C);
}